// round 1
// baseline (speedup 1.0000x reference)
#include <cuda_runtime.h>

#define N_NODES 100000
#define E_EDGES 3200000
#define IN_DIM  256
#define OUT_DIM 64
#define NEG_SLOPE 0.01f
#define LN_EPS   1e-5f

// Scratch (allocation-free rule: __device__ globals)
__device__ float g_h[(size_t)N_NODES * OUT_DIM];   // x @ W
__device__ float g_deg[N_NODES];
__device__ float g_dinv[N_NODES];

// ---------------------------------------------------------------------------
// K1: deg init to 1.0 (self-loop weight)
__global__ void k_deg_init() {
    int i = blockIdx.x * blockDim.x + threadIdx.x;
    if (i < N_NODES) g_deg[i] = 1.0f;
}

// K2: deg[dst] += ew  (spread int-addressed float atomics, cheap)
__global__ void k_deg_accum(const int* __restrict__ ei, const float* __restrict__ ew) {
    int e = blockIdx.x * blockDim.x + threadIdx.x;
    if (e < E_EDGES) {
        atomicAdd(&g_deg[ei[E_EDGES + e]], ew[e]);
    }
}

// K3: dinv = rsqrt(deg)   (deg >= 1 always)
__global__ void k_dinv() {
    int i = blockIdx.x * blockDim.x + threadIdx.x;
    if (i < N_NODES) g_dinv[i] = rsqrtf(g_deg[i]);
}

// ---------------------------------------------------------------------------
// K4: GEMM h = x @ W, 64x64 tile per 256-thread block, 4x4 per thread.
// Also writes d_out[n] = h[n] * dinv[n]^2  (self-loop term) as scatter init.
#define KC 32
__global__ __launch_bounds__(256) void k_gemm(const float* __restrict__ x,
                                              const float* __restrict__ W,
                                              float* __restrict__ out) {
    __shared__ float sx[64][KC + 1];   // rows x k (padded)
    __shared__ float sw[KC][OUT_DIM];  // k x cols

    const int tid = threadIdx.x;
    const int tx = tid & 15;           // col group: cols 4*tx .. 4*tx+3
    const int ty = tid >> 4;           // row group: rows 4*ty .. 4*ty+3
    const int row0 = blockIdx.x * 64;

    float acc[4][4];
#pragma unroll
    for (int i = 0; i < 4; i++)
#pragma unroll
        for (int j = 0; j < 4; j++) acc[i][j] = 0.0f;

    for (int k0 = 0; k0 < IN_DIM; k0 += KC) {
        // load x tile: 64 x 32 = 2048 floats, 8 per thread, coalesced along k
#pragma unroll
        for (int i = 0; i < 8; i++) {
            int idx = tid + i * 256;
            int r = idx >> 5;          // 0..63
            int c = idx & 31;          // 0..31
            int row = row0 + r;
            sx[r][c] = (row < N_NODES) ? x[(size_t)row * IN_DIM + k0 + c] : 0.0f;
        }
        // load W tile: 32 x 64 = 2048 floats, coalesced along cols
#pragma unroll
        for (int i = 0; i < 8; i++) {
            int idx = tid + i * 256;
            int r = idx >> 6;          // 0..31
            int c = idx & 63;          // 0..63
            sw[r][c] = W[(size_t)(k0 + r) * OUT_DIM + c];
        }
        __syncthreads();

#pragma unroll
        for (int kk = 0; kk < KC; kk++) {
            float4 wv = *reinterpret_cast<const float4*>(&sw[kk][4 * tx]);
            float a0 = sx[4 * ty + 0][kk];
            float a1 = sx[4 * ty + 1][kk];
            float a2 = sx[4 * ty + 2][kk];
            float a3 = sx[4 * ty + 3][kk];
            acc[0][0] += a0 * wv.x; acc[0][1] += a0 * wv.y; acc[0][2] += a0 * wv.z; acc[0][3] += a0 * wv.w;
            acc[1][0] += a1 * wv.x; acc[1][1] += a1 * wv.y; acc[1][2] += a1 * wv.z; acc[1][3] += a1 * wv.w;
            acc[2][0] += a2 * wv.x; acc[2][1] += a2 * wv.y; acc[2][2] += a2 * wv.z; acc[2][3] += a2 * wv.w;
            acc[3][0] += a3 * wv.x; acc[3][1] += a3 * wv.y; acc[3][2] += a3 * wv.z; acc[3][3] += a3 * wv.w;
        }
        __syncthreads();
    }

#pragma unroll
    for (int i = 0; i < 4; i++) {
        int row = row0 + 4 * ty + i;
        if (row < N_NODES) {
            float di = g_dinv[row];
            float di2 = di * di;
            float4 h4 = make_float4(acc[i][0], acc[i][1], acc[i][2], acc[i][3]);
            float4 o4 = make_float4(h4.x * di2, h4.y * di2, h4.z * di2, h4.w * di2);
            *reinterpret_cast<float4*>(&g_h[(size_t)row * OUT_DIM + 4 * tx]) = h4;
            *reinterpret_cast<float4*>(&out[(size_t)row * OUT_DIM + 4 * tx]) = o4;
        }
    }
}

// ---------------------------------------------------------------------------
// K5: edge scatter. One warp per edge; lane handles features {lane, lane+32}.
__global__ __launch_bounds__(256) void k_scatter(const int* __restrict__ ei,
                                                 const float* __restrict__ ew,
                                                 float* __restrict__ out) {
    int warp = (blockIdx.x * blockDim.x + threadIdx.x) >> 5;
    int lane = threadIdx.x & 31;
    if (warp >= E_EDGES) return;
    int s = ei[warp];
    int d = ei[E_EDGES + warp];
    float norm = g_dinv[s] * ew[warp] * g_dinv[d];
    const float* hs = &g_h[(size_t)s * OUT_DIM];
    float v0 = hs[lane] * norm;
    float v1 = hs[lane + 32] * norm;
    float* od = &out[(size_t)d * OUT_DIM];
    atomicAdd(&od[lane], v0);
    atomicAdd(&od[lane + 32], v1);
}

// ---------------------------------------------------------------------------
// K6: + bias, leaky relu, LayerNorm over 64. One warp per row.
__global__ __launch_bounds__(256) void k_ln(float* __restrict__ out,
                                            const float* __restrict__ b,
                                            const float* __restrict__ gamma,
                                            const float* __restrict__ beta) {
    int row = (blockIdx.x * blockDim.x + threadIdx.x) >> 5;
    int lane = threadIdx.x & 31;
    if (row >= N_NODES) return;
    float* r = out + (size_t)row * OUT_DIM;
    float y0 = r[lane] + b[lane];
    float y1 = r[lane + 32] + b[lane + 32];
    y0 = (y0 >= 0.0f) ? y0 : NEG_SLOPE * y0;
    y1 = (y1 >= 0.0f) ? y1 : NEG_SLOPE * y1;
    float s = y0 + y1;
#pragma unroll
    for (int o = 16; o > 0; o >>= 1) s += __shfl_xor_sync(0xFFFFFFFFu, s, o);
    float mu = s * (1.0f / OUT_DIM);
    float d0 = y0 - mu, d1 = y1 - mu;
    float vs = d0 * d0 + d1 * d1;
#pragma unroll
    for (int o = 16; o > 0; o >>= 1) vs += __shfl_xor_sync(0xFFFFFFFFu, vs, o);
    float rstd = rsqrtf(vs * (1.0f / OUT_DIM) + LN_EPS);
    r[lane]      = d0 * rstd * gamma[lane]      + beta[lane];
    r[lane + 32] = d1 * rstd * gamma[lane + 32] + beta[lane + 32];
}

// ---------------------------------------------------------------------------
extern "C" void kernel_launch(void* const* d_in, const int* in_sizes, int n_in,
                              void* d_out, int out_size) {
    const float* x     = (const float*)d_in[0];
    const int*   ei    = (const int*)  d_in[1];
    const float* ew    = (const float*)d_in[2];
    const float* W     = (const float*)d_in[3];
    const float* b     = (const float*)d_in[4];
    const float* gamma = (const float*)d_in[5];
    const float* beta  = (const float*)d_in[6];
    float* out = (float*)d_out;

    k_deg_init<<<(N_NODES + 255) / 256, 256>>>();
    k_deg_accum<<<(E_EDGES + 255) / 256, 256>>>(ei, ew);
    k_dinv<<<(N_NODES + 255) / 256, 256>>>();
    k_gemm<<<(N_NODES + 63) / 64, 256>>>(x, W, out);
    {
        long long threads = (long long)E_EDGES * 32;
        int blocks = (int)((threads + 255) / 256);
        k_scatter<<<blocks, 256>>>(ei, ew, out);
    }
    {
        long long threads = (long long)N_NODES * 32;
        int blocks = (int)((threads + 255) / 256);
        k_ln<<<blocks, 256>>>(out, b, gamma, beta);
    }
}

// round 2
// speedup vs baseline: 1.3713x; 1.3713x over previous
#include <cuda_runtime.h>

#define N_NODES 100000
#define E_EDGES 3200000
#define IN_DIM  256
#define OUT_DIM 64
#define NEG_SLOPE 0.01f
#define LN_EPS   1e-5f

// Scratch (allocation-free rule: __device__ globals)
__device__ float g_h[(size_t)N_NODES * OUT_DIM];   // x @ W
__device__ float g_deg[N_NODES];
__device__ float g_dinv[N_NODES];
__device__ float g_norm[E_EDGES];                  // dinv[s]*ew*dinv[d]

// ---------------------------------------------------------------------------
// K1: deg init to 1.0 (self-loop weight)
__global__ void k_deg_init() {
    int i = blockIdx.x * blockDim.x + threadIdx.x;
    if (i < N_NODES) g_deg[i] = 1.0f;
}

// K2: deg[dst] += ew  (spread scalar float atomics, cheap)
__global__ void k_deg_accum(const int* __restrict__ ei, const float* __restrict__ ew) {
    int e = blockIdx.x * blockDim.x + threadIdx.x;
    if (e < E_EDGES) {
        atomicAdd(&g_deg[ei[E_EDGES + e]], ew[e]);
    }
}

// K3: dinv = rsqrt(deg)   (deg >= 1 always)
__global__ void k_dinv() {
    int i = blockIdx.x * blockDim.x + threadIdx.x;
    if (i < N_NODES) g_dinv[i] = rsqrtf(g_deg[i]);
}

// K3b: per-edge norm = dinv[s] * ew * dinv[d]
__global__ void k_norm(const int* __restrict__ ei, const float* __restrict__ ew) {
    int e = blockIdx.x * blockDim.x + threadIdx.x;
    if (e < E_EDGES) {
        int s = ei[e];
        int d = ei[E_EDGES + e];
        g_norm[e] = g_dinv[s] * ew[e] * g_dinv[d];
    }
}

// ---------------------------------------------------------------------------
// K4: GEMM h = x @ W, 64x64 tile per 256-thread block, 4x4 per thread.
// Also writes d_out[n] = h[n] * dinv[n]^2  (self-loop term) as scatter init.
#define KC 32
__global__ __launch_bounds__(256) void k_gemm(const float* __restrict__ x,
                                              const float* __restrict__ W,
                                              float* __restrict__ out) {
    __shared__ float sx[64][KC + 1];   // rows x k (padded)
    __shared__ float sw[KC][OUT_DIM];  // k x cols

    const int tid = threadIdx.x;
    const int tx = tid & 15;           // col group: cols 4*tx .. 4*tx+3
    const int ty = tid >> 4;           // row group: rows 4*ty .. 4*ty+3
    const int row0 = blockIdx.x * 64;

    float acc[4][4];
#pragma unroll
    for (int i = 0; i < 4; i++)
#pragma unroll
        for (int j = 0; j < 4; j++) acc[i][j] = 0.0f;

    for (int k0 = 0; k0 < IN_DIM; k0 += KC) {
#pragma unroll
        for (int i = 0; i < 8; i++) {
            int idx = tid + i * 256;
            int r = idx >> 5;          // 0..63
            int c = idx & 31;          // 0..31
            int row = row0 + r;
            sx[r][c] = (row < N_NODES) ? x[(size_t)row * IN_DIM + k0 + c] : 0.0f;
        }
#pragma unroll
        for (int i = 0; i < 8; i++) {
            int idx = tid + i * 256;
            int r = idx >> 6;          // 0..31
            int c = idx & 63;          // 0..63
            sw[r][c] = W[(size_t)(k0 + r) * OUT_DIM + c];
        }
        __syncthreads();

#pragma unroll
        for (int kk = 0; kk < KC; kk++) {
            float4 wv = *reinterpret_cast<const float4*>(&sw[kk][4 * tx]);
            float a0 = sx[4 * ty + 0][kk];
            float a1 = sx[4 * ty + 1][kk];
            float a2 = sx[4 * ty + 2][kk];
            float a3 = sx[4 * ty + 3][kk];
            acc[0][0] += a0 * wv.x; acc[0][1] += a0 * wv.y; acc[0][2] += a0 * wv.z; acc[0][3] += a0 * wv.w;
            acc[1][0] += a1 * wv.x; acc[1][1] += a1 * wv.y; acc[1][2] += a1 * wv.z; acc[1][3] += a1 * wv.w;
            acc[2][0] += a2 * wv.x; acc[2][1] += a2 * wv.y; acc[2][2] += a2 * wv.z; acc[2][3] += a2 * wv.w;
            acc[3][0] += a3 * wv.x; acc[3][1] += a3 * wv.y; acc[3][2] += a3 * wv.z; acc[3][3] += a3 * wv.w;
        }
        __syncthreads();
    }

#pragma unroll
    for (int i = 0; i < 4; i++) {
        int row = row0 + 4 * ty + i;
        if (row < N_NODES) {
            float di = g_dinv[row];
            float di2 = di * di;
            float4 h4 = make_float4(acc[i][0], acc[i][1], acc[i][2], acc[i][3]);
            float4 o4 = make_float4(h4.x * di2, h4.y * di2, h4.z * di2, h4.w * di2);
            *reinterpret_cast<float4*>(&g_h[(size_t)row * OUT_DIM + 4 * tx]) = h4;
            *reinterpret_cast<float4*>(&out[(size_t)row * OUT_DIM + 4 * tx]) = o4;
        }
    }
}

// ---------------------------------------------------------------------------
// K5: edge scatter. 16 threads per edge; each thread handles one float4
// feature chunk via vectorized reduction (red.global.add.v4.f32, sm_90+).
__global__ __launch_bounds__(256) void k_scatter(const int* __restrict__ ei,
                                                 float* __restrict__ out) {
    long long t = (long long)blockIdx.x * blockDim.x + threadIdx.x;
    int e = (int)(t >> 4);
    int c = (int)(t & 15);           // float4 chunk 0..15
    if (e >= E_EDGES) return;
    int s = ei[e];                   // broadcast within 16-thread group
    int d = ei[E_EDGES + e];
    float norm = g_norm[e];
    float4 v = *reinterpret_cast<const float4*>(&g_h[(size_t)s * OUT_DIM + 4 * c]);
    v.x *= norm; v.y *= norm; v.z *= norm; v.w *= norm;
    float* dst = &out[(size_t)d * OUT_DIM + 4 * c];
    asm volatile("red.global.add.v4.f32 [%0], {%1, %2, %3, %4};"
                 :: "l"(dst), "f"(v.x), "f"(v.y), "f"(v.z), "f"(v.w)
                 : "memory");
}

// ---------------------------------------------------------------------------
// K6: + bias, leaky relu, LayerNorm over 64. One warp per row.
__global__ __launch_bounds__(256) void k_ln(float* __restrict__ out,
                                            const float* __restrict__ b,
                                            const float* __restrict__ gamma,
                                            const float* __restrict__ beta) {
    int row = (blockIdx.x * blockDim.x + threadIdx.x) >> 5;
    int lane = threadIdx.x & 31;
    if (row >= N_NODES) return;
    float* r = out + (size_t)row * OUT_DIM;
    float y0 = r[lane] + b[lane];
    float y1 = r[lane + 32] + b[lane + 32];
    y0 = (y0 >= 0.0f) ? y0 : NEG_SLOPE * y0;
    y1 = (y1 >= 0.0f) ? y1 : NEG_SLOPE * y1;
    float s = y0 + y1;
#pragma unroll
    for (int o = 16; o > 0; o >>= 1) s += __shfl_xor_sync(0xFFFFFFFFu, s, o);
    float mu = s * (1.0f / OUT_DIM);
    float d0 = y0 - mu, d1 = y1 - mu;
    float vs = d0 * d0 + d1 * d1;
#pragma unroll
    for (int o = 16; o > 0; o >>= 1) vs += __shfl_xor_sync(0xFFFFFFFFu, vs, o);
    float rstd = rsqrtf(vs * (1.0f / OUT_DIM) + LN_EPS);
    r[lane]      = d0 * rstd * gamma[lane]      + beta[lane];
    r[lane + 32] = d1 * rstd * gamma[lane + 32] + beta[lane + 32];
}

// ---------------------------------------------------------------------------
extern "C" void kernel_launch(void* const* d_in, const int* in_sizes, int n_in,
                              void* d_out, int out_size) {
    const float* x     = (const float*)d_in[0];
    const int*   ei    = (const int*)  d_in[1];
    const float* ew    = (const float*)d_in[2];
    const float* W     = (const float*)d_in[3];
    const float* b     = (const float*)d_in[4];
    const float* gamma = (const float*)d_in[5];
    const float* beta  = (const float*)d_in[6];
    float* out = (float*)d_out;

    k_deg_init<<<(N_NODES + 255) / 256, 256>>>();
    k_deg_accum<<<(E_EDGES + 255) / 256, 256>>>(ei, ew);
    k_dinv<<<(N_NODES + 255) / 256, 256>>>();
    k_norm<<<(E_EDGES + 255) / 256, 256>>>(ei, ew);
    k_gemm<<<(N_NODES + 63) / 64, 256>>>(x, W, out);
    {
        long long threads = (long long)E_EDGES * 16;
        int blocks = (int)((threads + 255) / 256);
        k_scatter<<<blocks, 256>>>(ei, out);
    }
    {
        long long threads = (long long)N_NODES * 32;
        int blocks = (int)((threads + 255) / 256);
        k_ln<<<blocks, 256>>>(out, b, gamma, beta);
    }
}

// round 3
// speedup vs baseline: 1.4595x; 1.0643x over previous
#include <cuda_runtime.h>
#include <cstdint>

#define N_NODES 100000
#define E_EDGES 3200000
#define IN_DIM  256
#define OUT_DIM 64
#define NEG_SLOPE 0.01f
#define LN_EPS   1e-5f

// Scratch (allocation-free rule: __device__ globals)
__device__ float g_h[(size_t)N_NODES * OUT_DIM];   // x @ W
__device__ float g_deg[N_NODES];
__device__ float g_dinv[N_NODES];

// ---------------------------------------------------------------------------
__global__ void k_deg_init() {
    int i = blockIdx.x * blockDim.x + threadIdx.x;
    if (i < N_NODES) g_deg[i] = 1.0f;
}

__global__ void k_deg_accum(const int* __restrict__ ei, const float* __restrict__ ew) {
    int e = blockIdx.x * blockDim.x + threadIdx.x;
    if (e < E_EDGES) {
        atomicAdd(&g_deg[ei[E_EDGES + e]], ew[e]);
    }
}

__global__ void k_dinv() {
    int i = blockIdx.x * blockDim.x + threadIdx.x;
    if (i < N_NODES) g_dinv[i] = rsqrtf(g_deg[i]);
}

// ---------------------------------------------------------------------------
// K4: GEMM h = x @ W via tensor cores (3xTF32 split for ~fp32 accuracy).
// Block: 256 threads = 8 warps. Tile M=128, N=64 (full). K chunked by 32.
// Each warp: rows 16w..16w+15, all 64 cols, via m16n8k8 mma.
// Epilogue also writes d_out[n] = h[n]*dinv[n]^2 (self-loop init for scatter).

__device__ __forceinline__ uint32_t f2tf32(float f) {
    uint32_t u;
    asm("cvt.rna.tf32.f32 %0, %1;" : "=r"(u) : "f"(f));
    return u;
}
__device__ __forceinline__ void split_tf32(float f, uint32_t& hi, uint32_t& lo) {
    hi = f2tf32(f);
    lo = f2tf32(f - __uint_as_float(hi));
}
__device__ __forceinline__ void mma1688(float* c, uint32_t a0, uint32_t a1,
                                        uint32_t a2, uint32_t a3,
                                        uint32_t b0, uint32_t b1) {
    asm volatile(
        "mma.sync.aligned.m16n8k8.row.col.f32.tf32.tf32.f32 "
        "{%0,%1,%2,%3}, {%4,%5,%6,%7}, {%8,%9}, {%0,%1,%2,%3};"
        : "+f"(c[0]), "+f"(c[1]), "+f"(c[2]), "+f"(c[3])
        : "r"(a0), "r"(a1), "r"(a2), "r"(a3), "r"(b0), "r"(b1));
}

#define SXS 36   // sX stride: bank = (4g + t) & 31, conflict-free frag loads
#define SWS 72   // sW stride: bank = (8t + g) & 31, conflict-free frag loads

__global__ __launch_bounds__(256) void k_gemm(const float* __restrict__ x,
                                              const float* __restrict__ W,
                                              float* __restrict__ out) {
    __shared__ float sX[128][SXS];   // 128 rows x 32 k (fp32, convert at use)
    __shared__ float sW[32][SWS];    // 32 k x 64 n

    const int tid  = threadIdx.x;
    const int warp = tid >> 5;
    const int lane = tid & 31;
    const int g = lane >> 2;         // 0..7
    const int t = lane & 3;          // 0..3
    const int row0 = blockIdx.x * 128;
    const int wr = warp * 16;        // warp row base within tile

    float acc[8][4];
#pragma unroll
    for (int nt = 0; nt < 8; nt++)
#pragma unroll
        for (int j = 0; j < 4; j++) acc[nt][j] = 0.0f;

    for (int k0 = 0; k0 < IN_DIM; k0 += 32) {
        // load x tile 128x32 (16 elems/thread, coalesced along k)
#pragma unroll
        for (int i = 0; i < 16; i++) {
            int idx = tid + i * 256;
            int r = idx >> 5;
            int c = idx & 31;
            int row = row0 + r;
            sX[r][c] = (row < N_NODES) ? x[(size_t)row * IN_DIM + k0 + c] : 0.0f;
        }
        // load W chunk 32x64 (8 elems/thread, coalesced along n)
#pragma unroll
        for (int i = 0; i < 8; i++) {
            int idx = tid + i * 256;
            int r = idx >> 6;
            int c = idx & 63;
            sW[r][c] = W[(size_t)(k0 + r) * OUT_DIM + c];
        }
        __syncthreads();

#pragma unroll
        for (int kc = 0; kc < 32; kc += 8) {
            // A fragment (rows wr+g, wr+g+8; cols kc+t, kc+t+4), hi/lo split
            uint32_t ah[4], al[4];
            split_tf32(sX[wr + g][kc + t],          ah[0], al[0]);
            split_tf32(sX[wr + g + 8][kc + t],      ah[1], al[1]);
            split_tf32(sX[wr + g][kc + t + 4],      ah[2], al[2]);
            split_tf32(sX[wr + g + 8][kc + t + 4],  ah[3], al[3]);

#pragma unroll
            for (int nt = 0; nt < 8; nt++) {
                int n0 = nt * 8;
                uint32_t bh0, bl0, bh1, bl1;
                split_tf32(sW[kc + t][n0 + g],     bh0, bl0);
                split_tf32(sW[kc + t + 4][n0 + g], bh1, bl1);
                mma1688(acc[nt], ah[0], ah[1], ah[2], ah[3], bh0, bh1);  // hi*hi
                mma1688(acc[nt], ah[0], ah[1], ah[2], ah[3], bl0, bl1);  // hi*lo
                mma1688(acc[nt], al[0], al[1], al[2], al[3], bh0, bh1);  // lo*hi
            }
        }
        __syncthreads();
    }

    // Epilogue: c layout per nt: c0=(g, 2t), c1=(g, 2t+1), c2=(g+8, 2t), c3=(g+8, 2t+1)
    int r_a = row0 + wr + g;
    int r_b = r_a + 8;
    float di2a = 0.0f, di2b = 0.0f;
    if (r_a < N_NODES) { float di = g_dinv[r_a]; di2a = di * di; }
    if (r_b < N_NODES) { float di = g_dinv[r_b]; di2b = di * di; }
#pragma unroll
    for (int nt = 0; nt < 8; nt++) {
        int col = nt * 8 + 2 * t;
        if (r_a < N_NODES) {
            float2 h2 = make_float2(acc[nt][0], acc[nt][1]);
            *reinterpret_cast<float2*>(&g_h[(size_t)r_a * OUT_DIM + col]) = h2;
            *reinterpret_cast<float2*>(&out[(size_t)r_a * OUT_DIM + col]) =
                make_float2(h2.x * di2a, h2.y * di2a);
        }
        if (r_b < N_NODES) {
            float2 h2 = make_float2(acc[nt][2], acc[nt][3]);
            *reinterpret_cast<float2*>(&g_h[(size_t)r_b * OUT_DIM + col]) = h2;
            *reinterpret_cast<float2*>(&out[(size_t)r_b * OUT_DIM + col]) =
                make_float2(h2.x * di2b, h2.y * di2b);
        }
    }
}

// ---------------------------------------------------------------------------
// K5: edge scatter. 16 threads per edge. Group leader computes the per-edge
// norm (dinv[s]*ew*dinv[d]) and broadcasts via shfl; each thread does one
// float4 gather + one vectorized red.global.add.v4.f32.
__global__ __launch_bounds__(256) void k_scatter(const int* __restrict__ ei,
                                                 const float* __restrict__ ew,
                                                 float* __restrict__ out) {
    long long tt = (long long)blockIdx.x * blockDim.x + threadIdx.x;
    int e = (int)(tt >> 4);
    int c = (int)(tt & 15);           // float4 chunk 0..15
    if (e >= E_EDGES) return;
    int s = ei[e];                    // broadcast load within the group
    int d = ei[E_EDGES + e];
    float nrm = 0.0f;
    if (c == 0) nrm = g_dinv[s] * ew[e] * g_dinv[d];
    nrm = __shfl_sync(0xFFFFFFFFu, nrm, 0, 16);
    float4 v = *reinterpret_cast<const float4*>(&g_h[(size_t)s * OUT_DIM + 4 * c]);
    v.x *= nrm; v.y *= nrm; v.z *= nrm; v.w *= nrm;
    float* dst = &out[(size_t)d * OUT_DIM + 4 * c];
    asm volatile("red.global.add.v4.f32 [%0], {%1, %2, %3, %4};"
                 :: "l"(dst), "f"(v.x), "f"(v.y), "f"(v.z), "f"(v.w)
                 : "memory");
}

// ---------------------------------------------------------------------------
// K6: + bias, leaky relu, LayerNorm over 64. One warp per row.
__global__ __launch_bounds__(256) void k_ln(float* __restrict__ out,
                                            const float* __restrict__ b,
                                            const float* __restrict__ gamma,
                                            const float* __restrict__ beta) {
    int row = (blockIdx.x * blockDim.x + threadIdx.x) >> 5;
    int lane = threadIdx.x & 31;
    if (row >= N_NODES) return;
    float* r = out + (size_t)row * OUT_DIM;
    float y0 = r[lane] + b[lane];
    float y1 = r[lane + 32] + b[lane + 32];
    y0 = (y0 >= 0.0f) ? y0 : NEG_SLOPE * y0;
    y1 = (y1 >= 0.0f) ? y1 : NEG_SLOPE * y1;
    float s = y0 + y1;
#pragma unroll
    for (int o = 16; o > 0; o >>= 1) s += __shfl_xor_sync(0xFFFFFFFFu, s, o);
    float mu = s * (1.0f / OUT_DIM);
    float d0 = y0 - mu, d1 = y1 - mu;
    float vs = d0 * d0 + d1 * d1;
#pragma unroll
    for (int o = 16; o > 0; o >>= 1) vs += __shfl_xor_sync(0xFFFFFFFFu, vs, o);
    float rstd = rsqrtf(vs * (1.0f / OUT_DIM) + LN_EPS);
    r[lane]      = d0 * rstd * gamma[lane]      + beta[lane];
    r[lane + 32] = d1 * rstd * gamma[lane + 32] + beta[lane + 32];
}

// ---------------------------------------------------------------------------
extern "C" void kernel_launch(void* const* d_in, const int* in_sizes, int n_in,
                              void* d_out, int out_size) {
    const float* x     = (const float*)d_in[0];
    const int*   ei    = (const int*)  d_in[1];
    const float* ew    = (const float*)d_in[2];
    const float* W     = (const float*)d_in[3];
    const float* b     = (const float*)d_in[4];
    const float* gamma = (const float*)d_in[5];
    const float* beta  = (const float*)d_in[6];
    float* out = (float*)d_out;

    k_deg_init<<<(N_NODES + 255) / 256, 256>>>();
    k_deg_accum<<<(E_EDGES + 255) / 256, 256>>>(ei, ew);
    k_dinv<<<(N_NODES + 255) / 256, 256>>>();
    k_gemm<<<(N_NODES + 127) / 128, 256>>>(x, W, out);
    {
        long long threads = (long long)E_EDGES * 16;
        int blocks = (int)((threads + 255) / 256);
        k_scatter<<<blocks, 256>>>(ei, ew, out);
    }
    {
        long long threads = (long long)N_NODES * 32;
        int blocks = (int)((threads + 255) / 256);
        k_ln<<<blocks, 256>>>(out, b, gamma, beta);
    }
}

// round 4
// speedup vs baseline: 1.6550x; 1.1340x over previous
#include <cuda_runtime.h>
#include <cstdint>

#define N_NODES 100000
#define E_EDGES 3200000
#define IN_DIM  256
#define OUT_DIM 64
#define NEG_SLOPE 0.01f
#define LN_EPS   1e-5f
#define NBLK_SCAN 98   // ceil(100000/1024)

// ---------------------------------------------------------------------------
// Scratch (allocation-free rule: __device__ globals)
__device__ float g_h[(size_t)N_NODES * OUT_DIM];   // x @ W
__device__ float g_deg[N_NODES];
__device__ float g_dinv[N_NODES];
__device__ int   g_cnt[N_NODES];
__device__ int   g_fill[N_NODES];
__device__ int   g_rowstart[N_NODES + 1];
__device__ int   g_bsum[128];
__device__ int   g_boff[128];
__device__ uint2 g_edge[E_EDGES];                  // {src, bitcast(norm)} CSR-ordered
__device__ uint4 g_Wp[8192];                       // fragment-packed W hi/lo

// ---------------------------------------------------------------------------
// K0: per-call scratch init (deg=1 self-loop, counters zero)
__global__ void k_init() {
    int i = blockIdx.x * blockDim.x + threadIdx.x;
    if (i < N_NODES) { g_deg[i] = 1.0f; g_cnt[i] = 0; g_fill[i] = 0; }
}

// K1: deg[dst] += ew ; cnt[dst] += 1  (fused, one pass over dst)
__global__ void k_deg_cnt(const int* __restrict__ ei, const float* __restrict__ ew) {
    int e = blockIdx.x * blockDim.x + threadIdx.x;
    if (e < E_EDGES) {
        int d = ei[E_EDGES + e];
        atomicAdd(&g_deg[d], ew[e]);
        atomicAdd(&g_cnt[d], 1);
    }
}

// K2: dinv = rsqrt(deg)  (deg >= 1 always)
__global__ void k_dinv() {
    int i = blockIdx.x * blockDim.x + threadIdx.x;
    if (i < N_NODES) g_dinv[i] = rsqrtf(g_deg[i]);
}

// ---------------------------------------------------------------------------
// Exclusive prefix scan of g_cnt -> g_rowstart  (3 tiny kernels)
__global__ __launch_bounds__(1024) void k_scan1() {
    int i = blockIdx.x * 1024 + threadIdx.x;
    int lane = threadIdx.x & 31, w = threadIdx.x >> 5;
    int v = (i < N_NODES) ? g_cnt[i] : 0;
    int x = v;
#pragma unroll
    for (int o = 1; o < 32; o <<= 1) {
        int y = __shfl_up_sync(0xFFFFFFFFu, x, o);
        if (lane >= o) x += y;
    }
    __shared__ int ws[32];
    if (lane == 31) ws[w] = x;
    __syncthreads();
    if (w == 0) {
        int z = ws[lane];
#pragma unroll
        for (int o = 1; o < 32; o <<= 1) {
            int y = __shfl_up_sync(0xFFFFFFFFu, z, o);
            if (lane >= o) z += y;
        }
        ws[lane] = z;
    }
    __syncthreads();
    int incl = x + (w > 0 ? ws[w - 1] : 0);
    if (i < N_NODES) g_rowstart[i] = incl - v;      // exclusive (pre block-offset)
    if (threadIdx.x == 1023) g_bsum[blockIdx.x] = incl;
}

__global__ void k_scan2() {
    int t = threadIdx.x;                            // 128 threads
    int lane = t & 31, w = t >> 5;
    int v = (t < NBLK_SCAN) ? g_bsum[t] : 0;
    int x = v;
#pragma unroll
    for (int o = 1; o < 32; o <<= 1) {
        int y = __shfl_up_sync(0xFFFFFFFFu, x, o);
        if (lane >= o) x += y;
    }
    __shared__ int ws[4];
    if (lane == 31) ws[w] = x;
    __syncthreads();
    if (t == 0) {
        int run = 0;
#pragma unroll
        for (int k = 0; k < 4; k++) { int tmp = ws[k]; ws[k] = run; run += tmp; }
    }
    __syncthreads();
    x += ws[w];
    if (t < NBLK_SCAN) g_boff[t] = x - v;           // exclusive block offsets
}

__global__ void k_scan3() {
    int i = blockIdx.x * blockDim.x + threadIdx.x;
    if (i < N_NODES) g_rowstart[i] += g_boff[i >> 10];
    if (i == 0) g_rowstart[N_NODES] = E_EDGES;
}

// K3: CSR placement; packs {src, norm} per edge slot
__global__ void k_place(const int* __restrict__ ei, const float* __restrict__ ew) {
    int e = blockIdx.x * blockDim.x + threadIdx.x;
    if (e < E_EDGES) {
        int s = ei[e];
        int d = ei[E_EDGES + e];
        float nrm = g_dinv[s] * ew[e] * g_dinv[d];
        int pos = g_rowstart[d] + atomicAdd(&g_fill[d], 1);
        g_edge[pos] = make_uint2((unsigned)s, __float_as_uint(nrm));
    }
}

// ---------------------------------------------------------------------------
// TF32 helpers
__device__ __forceinline__ uint32_t f2tf32(float f) {
    uint32_t u;
    asm("cvt.rna.tf32.f32 %0, %1;" : "=r"(u) : "f"(f));
    return u;
}
__device__ __forceinline__ void split_tf32(float f, uint32_t& hi, uint32_t& lo) {
    hi = f2tf32(f);
    lo = f2tf32(f - __uint_as_float(hi));
}
__device__ __forceinline__ void mma1688(float* c, uint32_t a0, uint32_t a1,
                                        uint32_t a2, uint32_t a3,
                                        uint32_t b0, uint32_t b1) {
    asm volatile(
        "mma.sync.aligned.m16n8k8.row.col.f32.tf32.tf32.f32 "
        "{%0,%1,%2,%3}, {%4,%5,%6,%7}, {%8,%9}, {%0,%1,%2,%3};"
        : "+f"(c[0]), "+f"(c[1]), "+f"(c[2]), "+f"(c[3])
        : "r"(a0), "r"(a1), "r"(a2), "r"(a3), "r"(b0), "r"(b1));
}

// K4a: pre-split W into fragment-packed hi/lo (done once per call, trivial)
// idx = c*1024 + s*256 + n*4 + t ; rows k1=c*32+s*8+t, k2=k1+4 ; col n
__global__ void k_wsplit(const float* __restrict__ W) {
    int idx = blockIdx.x * blockDim.x + threadIdx.x;
    if (idx >= 8192) return;
    int t = idx & 3;
    int n = (idx >> 2) & 63;
    int s = (idx >> 8) & 3;
    int c = idx >> 10;
    int k1 = c * 32 + s * 8 + t;
    int k2 = k1 + 4;
    uint32_t h1, l1, h2, l2;
    split_tf32(W[(size_t)k1 * OUT_DIM + n], h1, l1);
    split_tf32(W[(size_t)k2 * OUT_DIM + n], h2, l2);
    g_Wp[idx] = make_uint4(h1, h2, l1, l2);
}

// K4b: GEMM h = x @ W via 3xTF32 mma. All cvts hoisted: W pre-split global,
// x split once at smem-store. Dynamic smem: sXp[128][36] uint2 + sWp[1024] uint4.
__global__ __launch_bounds__(256) void k_gemm(const float* __restrict__ x) {
    extern __shared__ char smem[];
    uint2* sXp = reinterpret_cast<uint2*>(smem);            // [128][36] {hi,lo}
    uint4* sWp = reinterpret_cast<uint4*>(smem + 128 * 36 * 8);  // [1024]

    const int tid  = threadIdx.x;
    const int warp = tid >> 5;
    const int lane = tid & 31;
    const int g = lane >> 2;         // 0..7
    const int t = lane & 3;          // 0..3
    const int row0 = blockIdx.x * 128;
    const int wr = warp * 16;

    float acc[8][4];
#pragma unroll
    for (int nt = 0; nt < 8; nt++)
#pragma unroll
        for (int j = 0; j < 4; j++) acc[nt][j] = 0.0f;

    for (int c = 0; c < 8; c++) {
        const int k0 = c * 32;
        // x tile 128x32: load, split, store packed (16/thread, coalesced on k)
#pragma unroll
        for (int i = 0; i < 16; i++) {
            int idx = tid + i * 256;
            int r = idx >> 5;
            int col = idx & 31;
            int row = row0 + r;
            float f = (row < N_NODES) ? x[(size_t)row * IN_DIM + k0 + col] : 0.0f;
            uint32_t hi, lo;
            split_tf32(f, hi, lo);
            sXp[r * 36 + col] = make_uint2(hi, lo);
        }
        // W packed slab copy (4 uint4/thread, coalesced)
#pragma unroll
        for (int i = 0; i < 4; i++) {
            int idx = tid + i * 256;
            sWp[idx] = g_Wp[c * 1024 + idx];
        }
        __syncthreads();

#pragma unroll
        for (int s = 0; s < 4; s++) {
            uint2 a00 = sXp[(wr + g) * 36 + 8 * s + t];        // row g,   k t
            uint2 a10 = sXp[(wr + g + 8) * 36 + 8 * s + t];    // row g+8, k t
            uint2 a01 = sXp[(wr + g) * 36 + 8 * s + t + 4];    // row g,   k t+4
            uint2 a11 = sXp[(wr + g + 8) * 36 + 8 * s + t + 4];
#pragma unroll
            for (int nt = 0; nt < 8; nt++) {
                uint4 bb = sWp[(s * 64 + nt * 8 + g) * 4 + t]; // {bh0,bh1,bl0,bl1}
                mma1688(acc[nt], a00.x, a10.x, a01.x, a11.x, bb.x, bb.y); // hi*hi
                mma1688(acc[nt], a00.x, a10.x, a01.x, a11.x, bb.z, bb.w); // hi*lo
                mma1688(acc[nt], a00.y, a10.y, a01.y, a11.y, bb.x, bb.y); // lo*hi
            }
        }
        __syncthreads();
    }

    // Epilogue: c0=(g,2t) c1=(g,2t+1) c2=(g+8,2t) c3=(g+8,2t+1), col base nt*8
    int r_a = row0 + wr + g;
    int r_b = r_a + 8;
#pragma unroll
    for (int nt = 0; nt < 8; nt++) {
        int col = nt * 8 + 2 * t;
        if (r_a < N_NODES)
            *reinterpret_cast<float2*>(&g_h[(size_t)r_a * OUT_DIM + col]) =
                make_float2(acc[nt][0], acc[nt][1]);
        if (r_b < N_NODES)
            *reinterpret_cast<float2*>(&g_h[(size_t)r_b * OUT_DIM + col]) =
                make_float2(acc[nt][2], acc[nt][3]);
    }
}

// ---------------------------------------------------------------------------
// K5: CSR gather + self-loop + bias + leaky-relu + LayerNorm (fully fused).
// One warp per dst row; lane owns features {lane, lane+32}; register accum.
__global__ __launch_bounds__(256) void k_gather(float* __restrict__ out,
                                                const float* __restrict__ b,
                                                const float* __restrict__ gamma,
                                                const float* __restrict__ beta) {
    int row = blockIdx.x * 8 + (threadIdx.x >> 5);
    int lane = threadIdx.x & 31;
    if (row >= N_NODES) return;

    int j   = g_rowstart[row];
    int end = g_rowstart[row + 1];

    float di = g_dinv[row];
    float self = di * di;
    float a0 = g_h[(size_t)row * OUT_DIM + lane] * self;
    float a1 = g_h[(size_t)row * OUT_DIM + lane + 32] * self;

    // 1-deep software pipeline on the edge record to overlap with h gather
    uint2 ed;
    if (j < end) ed = g_edge[j];
    while (j < end) {
        int   s   = (int)ed.x;
        float nrm = __uint_as_float(ed.y);
        int jn = j + 1;
        if (jn < end) ed = g_edge[jn];
        float h0 = g_h[(size_t)s * OUT_DIM + lane];
        float h1 = g_h[(size_t)s * OUT_DIM + lane + 32];
        a0 = fmaf(h0, nrm, a0);
        a1 = fmaf(h1, nrm, a1);
        j = jn;
    }

    // epilogue: bias, leaky relu, LayerNorm(64)
    float y0 = a0 + b[lane];
    float y1 = a1 + b[lane + 32];
    y0 = (y0 >= 0.0f) ? y0 : NEG_SLOPE * y0;
    y1 = (y1 >= 0.0f) ? y1 : NEG_SLOPE * y1;
    float ssum = y0 + y1;
#pragma unroll
    for (int o = 16; o > 0; o >>= 1) ssum += __shfl_xor_sync(0xFFFFFFFFu, ssum, o);
    float mu = ssum * (1.0f / OUT_DIM);
    float d0 = y0 - mu, d1 = y1 - mu;
    float vs = d0 * d0 + d1 * d1;
#pragma unroll
    for (int o = 16; o > 0; o >>= 1) vs += __shfl_xor_sync(0xFFFFFFFFu, vs, o);
    float rstd = rsqrtf(vs * (1.0f / OUT_DIM) + LN_EPS);
    float* r = out + (size_t)row * OUT_DIM;
    r[lane]      = d0 * rstd * gamma[lane]      + beta[lane];
    r[lane + 32] = d1 * rstd * gamma[lane + 32] + beta[lane + 32];
}

// ---------------------------------------------------------------------------
extern "C" void kernel_launch(void* const* d_in, const int* in_sizes, int n_in,
                              void* d_out, int out_size) {
    const float* x     = (const float*)d_in[0];
    const int*   ei    = (const int*)  d_in[1];
    const float* ew    = (const float*)d_in[2];
    const float* W     = (const float*)d_in[3];
    const float* b     = (const float*)d_in[4];
    const float* gamma = (const float*)d_in[5];
    const float* beta  = (const float*)d_in[6];
    float* out = (float*)d_out;

    static bool attr_done = false;
    if (!attr_done) {
        cudaFuncSetAttribute(k_gemm, cudaFuncAttributeMaxDynamicSharedMemorySize,
                             128 * 36 * 8 + 1024 * 16);
        attr_done = true;
    }

    k_init<<<(N_NODES + 255) / 256, 256>>>();
    k_deg_cnt<<<(E_EDGES + 255) / 256, 256>>>(ei, ew);
    k_dinv<<<(N_NODES + 255) / 256, 256>>>();
    k_scan1<<<NBLK_SCAN, 1024>>>();
    k_scan2<<<1, 128>>>();
    k_scan3<<<(N_NODES + 255) / 256, 256>>>();
    k_place<<<(E_EDGES + 255) / 256, 256>>>(ei, ew);
    k_wsplit<<<8192 / 256, 256>>>(W);
    k_gemm<<<(N_NODES + 127) / 128, 256, 128 * 36 * 8 + 1024 * 16>>>(x);
    k_gather<<<(N_NODES + 7) / 8, 256>>>(out, b, gamma, beta);
}